// round 12
// baseline (speedup 1.0000x reference)
#include <cuda_runtime.h>

// LIF neuron Euler step (TemporalReceptiveField), pure elementwise, HBM-bound.
// R11: plateau-confirmed at ~6.2 TB/s mixed R/W HBM ceiling (5 configs agree).
// This is R3's best per-thread shape (2x float4, 6 front-batched LDG.128,
// .cs streaming on all 6 loads + 6 stores) with 512-thread blocks -> 4096
// blocks (half the dispatch count), exact cover, 32 regs, occ ~78%.

#define DT           0.001f
#define TAU_SYN_INV  200.0f
#define V_TH         1.0f

static constexpr int N_ELEMS = 16 * 64 * 128 * 128;   // 16,777,216
static constexpr int N4      = N_ELEMS / 4;           // 4,194,304 float4s
static constexpr int THREADS = 512;
static constexpr int PER_BLK = THREADS * 2;           // 1024 float4s per block
static constexpr int BLOCKS  = N4 / PER_BLK;          // 4096, exact cover

__device__ __forceinline__ void lif4(const float4 xv, const float4 vv, const float4 iv,
                                     const float dt_tau, const float syn_k,
                                     float4& zr, float4& vr, float4& ir)
{
    {
        float vd = fmaf(dt_tau, iv.x - vv.x, vv.x);
        float z  = (vd - V_TH > 0.0f) ? 1.0f : 0.0f;
        zr.x = z;  vr.x = (z > 0.0f) ? 0.0f : vd;
        ir.x = (iv.x - syn_k * iv.x) + xv.x;
    }
    {
        float vd = fmaf(dt_tau, iv.y - vv.y, vv.y);
        float z  = (vd - V_TH > 0.0f) ? 1.0f : 0.0f;
        zr.y = z;  vr.y = (z > 0.0f) ? 0.0f : vd;
        ir.y = (iv.y - syn_k * iv.y) + xv.y;
    }
    {
        float vd = fmaf(dt_tau, iv.z - vv.z, vv.z);
        float z  = (vd - V_TH > 0.0f) ? 1.0f : 0.0f;
        zr.z = z;  vr.z = (z > 0.0f) ? 0.0f : vd;
        ir.z = (iv.z - syn_k * iv.z) + xv.z;
    }
    {
        float vd = fmaf(dt_tau, iv.w - vv.w, vv.w);
        float z  = (vd - V_TH > 0.0f) ? 1.0f : 0.0f;
        zr.w = z;  vr.w = (z > 0.0f) ? 0.0f : vd;
        ir.w = (iv.w - syn_k * iv.w) + xv.w;
    }
}

__global__ __launch_bounds__(THREADS)
void lif_step_kernel(const float4* __restrict__ x,
                     const float4* __restrict__ v0,
                     const float4* __restrict__ i0,
                     const float*  __restrict__ ps,
                     float4* __restrict__ z_out,
                     float4* __restrict__ v_out,
                     float4* __restrict__ i_out)
{
    const int i0idx = blockIdx.x * PER_BLK + threadIdx.x;  // exact cover
    const int i1idx = i0idx + THREADS;

    // Front-batch all 6 loads (streaming: no reuse, evict-first).
    const float4 xv0 = __ldcs(x  + i0idx);
    const float4 vv0 = __ldcs(v0 + i0idx);
    const float4 iv0 = __ldcs(i0 + i0idx);
    const float4 xv1 = __ldcs(x  + i1idx);
    const float4 vv1 = __ldcs(v0 + i1idx);
    const float4 iv1 = __ldcs(i0 + i1idx);

    // channel = (element_index / (H*W)) % C  ->  (float4_index >> 12) & 63
    const float syn_k   = DT * TAU_SYN_INV;  // 0.2f, matching ref op order
    const float dt_tau0 = DT * __ldg(ps + ((i0idx >> 12) & 63));
    const float dt_tau1 = DT * __ldg(ps + ((i1idx >> 12) & 63));

    float4 zr0, vr0, ir0, zr1, vr1, ir1;
    lif4(xv0, vv0, iv0, dt_tau0, syn_k, zr0, vr0, ir0);
    lif4(xv1, vv1, iv1, dt_tau1, syn_k, zr1, vr1, ir1);

    __stcs(z_out + i0idx, zr0);
    __stcs(v_out + i0idx, vr0);
    __stcs(i_out + i0idx, ir0);
    __stcs(z_out + i1idx, zr1);
    __stcs(v_out + i1idx, vr1);
    __stcs(i_out + i1idx, ir1);
}

extern "C" void kernel_launch(void* const* d_in, const int* in_sizes, int n_in,
                              void* d_out, int out_size)
{
    const float4* x  = (const float4*)d_in[0];
    const float4* v0 = (const float4*)d_in[1];
    const float4* i0 = (const float4*)d_in[2];
    const float*  ps = (const float*)d_in[3];

    float* out = (float*)d_out;
    float4* z_out = (float4*)(out);
    float4* v_out = (float4*)(out + N_ELEMS);
    float4* i_out = (float4*)(out + 2 * N_ELEMS);

    lif_step_kernel<<<BLOCKS, THREADS>>>(x, v0, i0, ps, z_out, v_out, i_out);
}

// round 13
// speedup vs baseline: 1.0050x; 1.0050x over previous
#include <cuda_runtime.h>

// LIF neuron Euler step (TemporalReceptiveField), pure elementwise, HBM-bound.
// R12: roofline confirmed across 6 configs (56.3-58.8us kernel, 74-78% DRAM,
// ~6.1 TB/s = mixed 50/50 R/W HBM turnaround ceiling; traffic irreducible at
// ~400 MB/iter). This is the best-measured config (R3): 2x float4 per thread,
// 6 front-batched LDG.128, .cs streaming loads+stores, 256 thr x 8192 blocks,
// 32 regs, ~81% occ, kernel 56.3us.

#define DT           0.001f
#define TAU_SYN_INV  200.0f
#define V_TH         1.0f

static constexpr int N_ELEMS = 16 * 64 * 128 * 128;   // 16,777,216
static constexpr int N4      = N_ELEMS / 4;           // 4,194,304 float4s
static constexpr int THREADS = 256;
static constexpr int PER_BLK = THREADS * 2;           // 512 float4s per block
static constexpr int BLOCKS  = N4 / PER_BLK;          // 8192, exact cover

__device__ __forceinline__ void lif4(const float4 xv, const float4 vv, const float4 iv,
                                     const float dt_tau, const float syn_k,
                                     float4& zr, float4& vr, float4& ir)
{
    {
        float vd = fmaf(dt_tau, iv.x - vv.x, vv.x);
        float z  = (vd - V_TH > 0.0f) ? 1.0f : 0.0f;
        zr.x = z;  vr.x = (z > 0.0f) ? 0.0f : vd;
        ir.x = (iv.x - syn_k * iv.x) + xv.x;
    }
    {
        float vd = fmaf(dt_tau, iv.y - vv.y, vv.y);
        float z  = (vd - V_TH > 0.0f) ? 1.0f : 0.0f;
        zr.y = z;  vr.y = (z > 0.0f) ? 0.0f : vd;
        ir.y = (iv.y - syn_k * iv.y) + xv.y;
    }
    {
        float vd = fmaf(dt_tau, iv.z - vv.z, vv.z);
        float z  = (vd - V_TH > 0.0f) ? 1.0f : 0.0f;
        zr.z = z;  vr.z = (z > 0.0f) ? 0.0f : vd;
        ir.z = (iv.z - syn_k * iv.z) + xv.z;
    }
    {
        float vd = fmaf(dt_tau, iv.w - vv.w, vv.w);
        float z  = (vd - V_TH > 0.0f) ? 1.0f : 0.0f;
        zr.w = z;  vr.w = (z > 0.0f) ? 0.0f : vd;
        ir.w = (iv.w - syn_k * iv.w) + xv.w;
    }
}

__global__ __launch_bounds__(THREADS)
void lif_step_kernel(const float4* __restrict__ x,
                     const float4* __restrict__ v0,
                     const float4* __restrict__ i0,
                     const float*  __restrict__ ps,
                     float4* __restrict__ z_out,
                     float4* __restrict__ v_out,
                     float4* __restrict__ i_out)
{
    const int i0idx = blockIdx.x * PER_BLK + threadIdx.x;  // exact cover
    const int i1idx = i0idx + THREADS;

    // Front-batch all 6 loads (streaming: no reuse, evict-first).
    const float4 xv0 = __ldcs(x  + i0idx);
    const float4 vv0 = __ldcs(v0 + i0idx);
    const float4 iv0 = __ldcs(i0 + i0idx);
    const float4 xv1 = __ldcs(x  + i1idx);
    const float4 vv1 = __ldcs(v0 + i1idx);
    const float4 iv1 = __ldcs(i0 + i1idx);

    // channel = (element_index / (H*W)) % C  ->  (float4_index >> 12) & 63
    const float syn_k   = DT * TAU_SYN_INV;  // 0.2f, matching ref op order
    const float dt_tau0 = DT * __ldg(ps + ((i0idx >> 12) & 63));
    const float dt_tau1 = DT * __ldg(ps + ((i1idx >> 12) & 63));

    float4 zr0, vr0, ir0, zr1, vr1, ir1;
    lif4(xv0, vv0, iv0, dt_tau0, syn_k, zr0, vr0, ir0);
    lif4(xv1, vv1, iv1, dt_tau1, syn_k, zr1, vr1, ir1);

    __stcs(z_out + i0idx, zr0);
    __stcs(v_out + i0idx, vr0);
    __stcs(i_out + i0idx, ir0);
    __stcs(z_out + i1idx, zr1);
    __stcs(v_out + i1idx, vr1);
    __stcs(i_out + i1idx, ir1);
}

extern "C" void kernel_launch(void* const* d_in, const int* in_sizes, int n_in,
                              void* d_out, int out_size)
{
    const float4* x  = (const float4*)d_in[0];
    const float4* v0 = (const float4*)d_in[1];
    const float4* i0 = (const float4*)d_in[2];
    const float*  ps = (const float*)d_in[3];

    float* out = (float*)d_out;
    float4* z_out = (float4*)(out);
    float4* v_out = (float4*)(out + N_ELEMS);
    float4* i_out = (float4*)(out + 2 * N_ELEMS);

    lif_step_kernel<<<BLOCKS, THREADS>>>(x, v0, i0, ps, z_out, v_out, i_out);
}